// round 1
// baseline (speedup 1.0000x reference)
#include <cuda_runtime.h>
#include <cstddef>

#define BATCH 16384
#define DG    256
#define MT    64          // rows per CTA
#define NT    256         // threads per CTA
#define KC    32          // K chunk streamed through SMEM

// Persistent scratch (allocation-free rule: __device__ globals).
// g_bufs[0..8] = g0..g8, l_bufs[1..9] with l_bufs[9] permanently zero.
__device__ float g_bufs[9][BATCH * DG];
__device__ float l_bufs[10][BATCH * DG];
__device__ float h_buf[BATCH * DG];

__device__ __forceinline__ float sigm(float x) { return 1.0f / (1.0f + expf(-x)); }

// ---------------------------------------------------------------------------
// Load a MT x KTOT input tile into SMEM (row-major, stride KTOT).
// Supports a 2-source concat along K (each source supplies 256 columns).
// ---------------------------------------------------------------------------
template <int KTOT>
__device__ __forceinline__ void load_tile(float* sX,
                                          const float* __restrict__ A0, int lda0,
                                          const float* __restrict__ A1, int lda1,
                                          int rowbase) {
    const int tid = threadIdx.x;
    constexpr int C4 = KTOT / 4;            // float4 per row
    constexpr int ITERS = (MT * C4) / NT;
#pragma unroll
    for (int i = 0; i < ITERS; i++) {
        int e = i * NT + tid;
        int row = e / C4;
        int c = (e % C4) * 4;
        float4 v;
        if (KTOT == 256 || c < 256)
            v = *(const float4*)(A0 + (size_t)(rowbase + row) * lda0 + c);
        else
            v = *(const float4*)(A1 + (size_t)(rowbase + row) * lda1 + (c - 256));
        *(float4*)(sX + row * KTOT + c) = v;
    }
}

// ---------------------------------------------------------------------------
// Core GEMM: acc[4][16] (per thread) = sX[MT x KTOT] @ W[KTOT x N] tile.
// Threads: 16x16 (tx = col group of 16, ty = row group of 4).
// Weights streamed in KC-row chunks, double-buffered in SMEM.
// colbase selects a 256-wide column tile of W; columns >= N are zero-filled.
// ---------------------------------------------------------------------------
template <int KTOT>
__device__ __forceinline__ void gemm_core(float acc[4][16],
                                          const float* __restrict__ sX,
                                          float* sW,
                                          const float* __restrict__ W, int ldw,
                                          int colbase, int N) {
    const int tid = threadIdx.x;
    const int tx = tid & 15, ty = tid >> 4;
    const int rbase = ty * 4, cbase = tx * 16;

#pragma unroll
    for (int r = 0; r < 4; r++)
#pragma unroll
        for (int c = 0; c < 16; c++) acc[r][c] = 0.f;

    constexpr int NCH = KTOT / KC;

    // Preload chunk 0 into buffer 0.
#pragma unroll
    for (int i = 0; i < 8; i++) {
        int e = i * NT + tid;
        int k = e >> 6;
        int c = (e & 63) * 4;
        int col = colbase + c;
        float4 v = make_float4(0.f, 0.f, 0.f, 0.f);
        if (col < N) v = *(const float4*)(W + (size_t)k * ldw + col);
        *(float4*)(sW + k * 256 + c) = v;
    }
    __syncthreads();

    for (int ch = 0; ch < NCH; ++ch) {
        float4 wreg[8];
        if (ch + 1 < NCH) {
#pragma unroll
            for (int i = 0; i < 8; i++) {
                int e = i * NT + tid;
                int k = e >> 6;
                int c = (e & 63) * 4;
                int col = colbase + c;
                float4 v = make_float4(0.f, 0.f, 0.f, 0.f);
                if (col < N)
                    v = *(const float4*)(W + (size_t)((ch + 1) * KC + k) * ldw + col);
                wreg[i] = v;
            }
        }
        const float* sWc = sW + (ch & 1) * (KC * 256);
#pragma unroll 2
        for (int k4 = 0; k4 < KC / 4; ++k4) {
            // Vectorized A loads: 4 rows x 4 consecutive k
            float a_[4][4];
#pragma unroll
            for (int r = 0; r < 4; r++) {
                float4 A = *(const float4*)(sX + (rbase + r) * KTOT + ch * KC + k4 * 4);
                a_[r][0] = A.x; a_[r][1] = A.y; a_[r][2] = A.z; a_[r][3] = A.w;
            }
#pragma unroll
            for (int kk = 0; kk < 4; ++kk) {
                int k = k4 * 4 + kk;
#pragma unroll
                for (int j = 0; j < 4; j++) {
                    float4 b = *(const float4*)(sWc + k * 256 + cbase + j * 4);
#pragma unroll
                    for (int r = 0; r < 4; r++) {
                        acc[r][4 * j + 0] = fmaf(a_[r][kk], b.x, acc[r][4 * j + 0]);
                        acc[r][4 * j + 1] = fmaf(a_[r][kk], b.y, acc[r][4 * j + 1]);
                        acc[r][4 * j + 2] = fmaf(a_[r][kk], b.z, acc[r][4 * j + 2]);
                        acc[r][4 * j + 3] = fmaf(a_[r][kk], b.w, acc[r][4 * j + 3]);
                    }
                }
            }
        }
        __syncthreads();
        if (ch + 1 < NCH) {
            float* sWn = sW + ((ch + 1) & 1) * (KC * 256);
#pragma unroll
            for (int i = 0; i < 8; i++) {
                int e = i * NT + tid;
                int k = e >> 6;
                int c = (e & 63) * 4;
                *(float4*)(sWn + k * 256 + c) = wreg[i];
            }
            __syncthreads();
        }
    }
}

// ---------------------------------------------------------------------------
// Generic GEMM + bias (+ReLU) kernel.  out[MTxN tile] = act(A @ W + bias)
// ---------------------------------------------------------------------------
template <int KTOT, bool RELU>
__global__ __launch_bounds__(NT) void gemm_kernel(
    const float* __restrict__ A0, int lda0,
    const float* __restrict__ A1, int lda1,
    const float* __restrict__ W, int ldw,
    const float* __restrict__ bias,
    float* __restrict__ out, int ldout, int N) {
    extern __shared__ float smem[];
    float* sX = smem;                 // MT*KTOT
    float* sW = smem + MT * KTOT;     // 2*KC*256

    const int rowbase = blockIdx.x * MT;
    const int colbase = blockIdx.y * 256;

    load_tile<KTOT>(sX, A0, lda0, A1, lda1, rowbase);

    float acc[4][16];
    gemm_core<KTOT>(acc, sX, sW, W, ldw, colbase, N);

    const int tid = threadIdx.x, tx = tid & 15, ty = tid >> 4;
    const int r0 = rowbase + ty * 4;
#pragma unroll
    for (int r = 0; r < 4; r++) {
#pragma unroll
        for (int j = 0; j < 4; j++) {
            int col = colbase + tx * 16 + j * 4;
            if (col < N) {
                float4 bv = *(const float4*)(bias + col);
                float4 v;
                v.x = acc[r][4 * j + 0] + bv.x;
                v.y = acc[r][4 * j + 1] + bv.y;
                v.z = acc[r][4 * j + 2] + bv.z;
                v.w = acc[r][4 * j + 3] + bv.w;
                if (RELU) {
                    v.x = fmaxf(v.x, 0.f); v.y = fmaxf(v.y, 0.f);
                    v.z = fmaxf(v.z, 0.f); v.w = fmaxf(v.w, 0.f);
                }
                *(float4*)(out + (size_t)(r0 + r) * ldout + col) = v;
            }
        }
    }
}

// ---------------------------------------------------------------------------
// Fused plate kernel. One CTA handles MT rows through all plate phases.
//   e     = sigmoid(l @ W_eq + b_eq)
//   df    = g - e
//   delta = alpha * (df @ W_tr + b_tr)
//   DESC: out = l + delta @ W_ab + b_ab      ASC: out = g - delta
// ---------------------------------------------------------------------------
template <bool DESC>
__global__ __launch_bounds__(NT) void plate_kernel(
    const float* __restrict__ g_in, const float* __restrict__ l_in,
    float* __restrict__ out,
    const float* __restrict__ W_eq, const float* __restrict__ b_eq,
    const float* __restrict__ W_tr, const float* __restrict__ b_tr,
    const float* __restrict__ W_ab, const float* __restrict__ b_ab,
    const float* __restrict__ alpha_p) {
    extern __shared__ float smem[];
    float* sX = smem;               // MT*DG
    float* sW = smem + MT * DG;     // 2*KC*256

    const int rowbase = blockIdx.x * MT;
    const int tid = threadIdx.x, tx = tid & 15, ty = tid >> 4;
    const int r0l = ty * 4;
    float acc[4][16];

    // Phase 1: e = sigmoid(l @ W_eq + b_eq); df = g - e -> sX
    load_tile<DG>(sX, l_in, DG, nullptr, 0, rowbase);
    gemm_core<DG>(acc, sX, sW, W_eq, DG, 0, DG);
    __syncthreads();  // all reads of sX done

    const float alpha = __ldg(alpha_p);
#pragma unroll
    for (int r = 0; r < 4; r++) {
        int grow = rowbase + r0l + r;
#pragma unroll
        for (int j = 0; j < 4; j++) {
            int col = tx * 16 + j * 4;
            float4 gv = *(const float4*)(g_in + (size_t)grow * DG + col);
            float4 bv = *(const float4*)(b_eq + col);
            float4 d;
            d.x = gv.x - sigm(acc[r][4 * j + 0] + bv.x);
            d.y = gv.y - sigm(acc[r][4 * j + 1] + bv.y);
            d.z = gv.z - sigm(acc[r][4 * j + 2] + bv.z);
            d.w = gv.w - sigm(acc[r][4 * j + 3] + bv.w);
            *(float4*)(sX + (r0l + r) * DG + col) = d;
        }
    }
    __syncthreads();

    // Phase 2: delta = alpha * (df @ W_tr + b_tr)
    gemm_core<DG>(acc, sX, sW, W_tr, DG, 0, DG);

    if (!DESC) {
        // ASC: out = g - delta
#pragma unroll
        for (int r = 0; r < 4; r++) {
            int grow = rowbase + r0l + r;
#pragma unroll
            for (int j = 0; j < 4; j++) {
                int col = tx * 16 + j * 4;
                float4 gv = *(const float4*)(g_in + (size_t)grow * DG + col);
                float4 bt = *(const float4*)(b_tr + col);
                float4 v;
                v.x = gv.x - alpha * (acc[r][4 * j + 0] + bt.x);
                v.y = gv.y - alpha * (acc[r][4 * j + 1] + bt.y);
                v.z = gv.z - alpha * (acc[r][4 * j + 2] + bt.z);
                v.w = gv.w - alpha * (acc[r][4 * j + 3] + bt.w);
                *(float4*)(out + (size_t)grow * DG + col) = v;
            }
        }
    } else {
        // DESC: delta -> sX, then out = l + delta @ W_ab + b_ab
        __syncthreads();
#pragma unroll
        for (int r = 0; r < 4; r++) {
#pragma unroll
            for (int j = 0; j < 4; j++) {
                int col = tx * 16 + j * 4;
                float4 bt = *(const float4*)(b_tr + col);
                float4 d;
                d.x = alpha * (acc[r][4 * j + 0] + bt.x);
                d.y = alpha * (acc[r][4 * j + 1] + bt.y);
                d.z = alpha * (acc[r][4 * j + 2] + bt.z);
                d.w = alpha * (acc[r][4 * j + 3] + bt.w);
                *(float4*)(sX + (r0l + r) * DG + col) = d;
            }
        }
        __syncthreads();

        gemm_core<DG>(acc, sX, sW, W_ab, DG, 0, DG);
#pragma unroll
        for (int r = 0; r < 4; r++) {
            int grow = rowbase + r0l + r;
#pragma unroll
            for (int j = 0; j < 4; j++) {
                int col = tx * 16 + j * 4;
                float4 lv = *(const float4*)(l_in + (size_t)grow * DG + col);
                float4 ba = *(const float4*)(b_ab + col);
                float4 v;
                v.x = lv.x + acc[r][4 * j + 0] + ba.x;
                v.y = lv.y + acc[r][4 * j + 1] + ba.y;
                v.z = lv.z + acc[r][4 * j + 2] + ba.z;
                v.w = lv.w + acc[r][4 * j + 3] + ba.w;
                *(float4*)(out + (size_t)grow * DG + col) = v;
            }
        }
    }
}

// ---------------------------------------------------------------------------
extern "C" void kernel_launch(void* const* d_in, const int* in_sizes, int n_in,
                              void* d_out, int out_size) {
    (void)in_sizes; (void)n_in; (void)out_size;
    const float* x     = (const float*)d_in[0];
    const float* W_ge  = (const float*)d_in[1];
    const float* b_ge  = (const float*)d_in[2];
    const float* W_eq  = (const float*)d_in[3];
    const float* b_eq  = (const float*)d_in[4];
    const float* W_tr  = (const float*)d_in[5];
    const float* b_tr  = (const float*)d_in[6];
    const float* W_ab  = (const float*)d_in[7];
    const float* b_ab  = (const float*)d_in[8];
    const float* alpha = (const float*)d_in[9];
    const float* W1    = (const float*)d_in[10];
    const float* b1    = (const float*)d_in[11];
    const float* W2    = (const float*)d_in[12];
    const float* b2    = (const float*)d_in[13];
    float* out = (float*)d_out;

    float *gb = nullptr, *lb = nullptr, *hb = nullptr;
    cudaGetSymbolAddress((void**)&gb, g_bufs);
    cudaGetSymbolAddress((void**)&lb, l_bufs);
    cudaGetSymbolAddress((void**)&hb, h_buf);
    auto G = [&](int i) { return gb + (size_t)i * BATCH * DG; };
    auto L = [&](int i) { return lb + (size_t)i * BATCH * DG; };

    const size_t SM256 = (size_t)(MT * 256 + 2 * KC * 256) * sizeof(float);  // 128 KB
    const size_t SM512 = (size_t)(MT * 512 + 2 * KC * 256) * sizeof(float);  // 192 KB

    cudaFuncSetAttribute(gemm_kernel<512, true>,  cudaFuncAttributeMaxDynamicSharedMemorySize, (int)SM512);
    cudaFuncSetAttribute(gemm_kernel<256, false>, cudaFuncAttributeMaxDynamicSharedMemorySize, (int)SM256);
    cudaFuncSetAttribute(plate_kernel<true>,      cudaFuncAttributeMaxDynamicSharedMemorySize, (int)SM256);
    cudaFuncSetAttribute(plate_kernel<false>,     cudaFuncAttributeMaxDynamicSharedMemorySize, (int)SM256);

    // l[9] = 0 (read-only thereafter; reset each call for determinism)
    cudaMemsetAsync(L(9), 0, (size_t)BATCH * DG * sizeof(float));

    dim3 grid(BATCH / MT, 1);

    // Encoder: g0 = relu(x @ W_ge + b_ge), K = 512
    gemm_kernel<512, true><<<grid, NT, SM512>>>(x, 512, x + 256, 512,
                                                W_ge, 256, b_ge, G(0), 256, 256);

    // Sweep 1: descending (g[1..8] are None -> g_in = g0)
    for (int n = 8; n >= 1; --n)
        plate_kernel<true><<<grid, NT, SM256>>>(G(0), L(n + 1), L(n),
                                                W_eq, b_eq, W_tr, b_tr, W_ab, b_ab, alpha);
    // Sweep 1: ascending
    for (int n = 1; n <= 8; ++n)
        plate_kernel<false><<<grid, NT, SM256>>>(G(n - 1), L(n), G(n),
                                                 W_eq, b_eq, W_tr, b_tr, W_ab, b_ab, alpha);
    // Sweep 2: descending
    for (int n = 8; n >= 1; --n)
        plate_kernel<true><<<grid, NT, SM256>>>(G(n - 1), L(n + 1), L(n),
                                                W_eq, b_eq, W_tr, b_tr, W_ab, b_ab, alpha);
    // Sweep 2: ascending
    for (int n = 1; n <= 8; ++n)
        plate_kernel<false><<<grid, NT, SM256>>>(G(n - 1), L(n), G(n),
                                                 W_eq, b_eq, W_tr, b_tr, W_ab, b_ab, alpha);

    // Head layer 1: h = relu([g8 || l1] @ W1 + b1), K = 512
    gemm_kernel<512, true><<<grid, NT, SM512>>>(G(8), 256, L(1), 256,
                                                W1, 256, b1, hb, 256, 256);
    // Head layer 2: out = h @ W2 + b2, N = 1000
    dim3 grid2(BATCH / MT, 4);
    gemm_kernel<256, false><<<grid2, NT, SM256>>>(hb, 256, nullptr, 0,
                                                  W2, 1000, b2, out, 1000, 1000);
}

// round 3
// speedup vs baseline: 5.1972x; 5.1972x over previous
#include <cuda_runtime.h>
#include <cuda_bf16.h>
#include <cstdint>
#include <cstddef>

#define BATCH 16384
#define DG    256

// SMEM geometry
#define SA_STRIDE 260                              // fp32 elems per A row (pad 4)
#define SA_BYTES  (128 * SA_STRIDE * 4)            // 133,120
#define SB_ROW    80                               // bytes per B row (40 bf16, pad 8)
#define SB_HALF   (256 * SB_ROW)                   // 20,480 (hi or lo plane)
#define SB_BUF    (2 * SB_HALF)                    // 40,960 per chunk buffer
#define SB_BYTES  (2 * SB_BUF)                     // 81,920 double buffered
#define SMEM_TOTAL (SA_BYTES + SB_BYTES)           // 215,040

// ===========================================================================
// Global scratch (__device__ globals: allocation-free rule)
// ===========================================================================
__device__ float g_bufs[9][BATCH * DG];
__device__ float l_bufs[10][BATCH * DG];
// Transposed + bf16 hi/lo split weights, [hi plane][lo plane], row = n, col = k
__device__ __align__(128) __nv_bfloat16 WT_ge[2 * 256 * 512];
__device__ __align__(128) __nv_bfloat16 WT_eq[2 * 256 * 256];
__device__ __align__(128) __nv_bfloat16 WT_tr[2 * 256 * 256];
__device__ __align__(128) __nv_bfloat16 WT_ab[2 * 256 * 256];
__device__ __align__(128) __nv_bfloat16 WT_1 [2 * 256 * 512];
__device__ __align__(128) __nv_bfloat16 WT_2 [2 * 1024 * 256];   // N padded to 1024

__device__ __forceinline__ float sigm(float x) { return 1.0f / (1.0f + expf(-x)); }

__device__ __forceinline__ uint32_t smem_to_u32(const void* p) {
    uint32_t a;
    asm("{ .reg .u64 t; cvta.to.shared.u64 t, %1; cvt.u32.u64 %0, t; }" : "=r"(a) : "l"(p));
    return a;
}

#define CP_ASYNC16(dst_u32, src_ptr) \
    asm volatile("cp.async.cg.shared.global [%0], [%1], 16;" :: "r"(dst_u32), "l"(src_ptr))
#define CP_COMMIT() asm volatile("cp.async.commit_group;" ::: "memory")
#define CP_WAIT1()  asm volatile("cp.async.wait_group 1;" ::: "memory")
#define CP_WAIT0()  asm volatile("cp.async.wait_group 0;" ::: "memory")
#define LDS32(r, addr) asm volatile("ld.shared.b32 %0, [%1];" : "=r"(r) : "r"(addr))

#define MMA16816(d, a, b) \
    asm volatile("mma.sync.aligned.m16n8k16.row.col.f32.bf16.bf16.f32 " \
        "{%0,%1,%2,%3}, {%4,%5,%6,%7}, {%8,%9}, {%0,%1,%2,%3};" \
        : "+f"((d)[0]), "+f"((d)[1]), "+f"((d)[2]), "+f"((d)[3]) \
        : "r"((a)[0]), "r"((a)[1]), "r"((a)[2]), "r"((a)[3]), "r"((b)[0]), "r"((b)[1]))

__device__ __forceinline__ void split2(float2 x, uint32_t& h, uint32_t& l) {
    __nv_bfloat162 hp = __float22bfloat162_rn(x);
    float2 hf = __bfloat1622float2(hp);
    float2 r = make_float2(x.x - hf.x, x.y - hf.y);
    __nv_bfloat162 lp = __float22bfloat162_rn(r);
    h = *reinterpret_cast<uint32_t*>(&hp);
    l = *reinterpret_cast<uint32_t*>(&lp);
}

// ===========================================================================
// prep: transpose + split all weights into WT_* (row = n, col = k)
// ===========================================================================
__device__ __forceinline__ void split_store(__nv_bfloat16* dst, int plane_sz, int i, float w) {
    __nv_bfloat16 h = __float2bfloat16(w);
    float r = w - __bfloat162float(h);
    dst[i] = h;
    dst[plane_sz + i] = __float2bfloat16(r);
}

__global__ void prep_kernel(const float* __restrict__ Wge, const float* __restrict__ Weq,
                            const float* __restrict__ Wtr, const float* __restrict__ Wab,
                            const float* __restrict__ W1,  const float* __restrict__ W2) {
    int idx0 = blockIdx.x * 256 + threadIdx.x;
    int stride = gridDim.x * 256;
    for (int i = idx0; i < 256 * 512; i += stride) {   // [512k][256n] -> [256n][512k]
        int n = i >> 9, k = i & 511;
        split_store(WT_ge, 256 * 512, i, Wge[k * 256 + n]);
        split_store(WT_1,  256 * 512, i, W1 [k * 256 + n]);
    }
    for (int i = idx0; i < 256 * 256; i += stride) {
        int n = i >> 8, k = i & 255;
        split_store(WT_eq, 256 * 256, i, Weq[k * 256 + n]);
        split_store(WT_tr, 256 * 256, i, Wtr[k * 256 + n]);
        split_store(WT_ab, 256 * 256, i, Wab[k * 256 + n]);
    }
    for (int i = idx0; i < 1024 * 256; i += stride) {  // [256k][1000n] -> [1024n][256k]
        int n = i >> 8, k = i & 255;
        float w = (n < 1000) ? W2[k * 1000 + n] : 0.0f;
        split_store(WT_2, 1024 * 256, i, w);
    }
}

// ===========================================================================
// HMMA GEMM core: acc[2][16][4] += sA[128 x 256 fp32] @ W^T (bf16x3 split)
// W given as hi/lo planes, layout [n][k] with row stride ldk.
// B streamed in K=32 chunks via cp.async, double buffered.
// Ends with __syncthreads (safe to write sA right after).
// ===========================================================================
__device__ __forceinline__ void issue_chunk(uint32_t sB, int buf,
                                            const __nv_bfloat16* __restrict__ hi,
                                            const __nv_bfloat16* __restrict__ lo,
                                            int ldk, int kbase, int tid) {
    uint32_t dst = sB + (uint32_t)buf * SB_BUF;
#pragma unroll
    for (int j = 0; j < 4; j++) {
        int e = j * 256 + tid;
        int n = e >> 2, seg = e & 3;
        CP_ASYNC16(dst + n * SB_ROW + seg * 16, hi + (size_t)n * ldk + kbase + seg * 8);
    }
#pragma unroll
    for (int j = 0; j < 4; j++) {
        int e = j * 256 + tid;
        int n = e >> 2, seg = e & 3;
        CP_ASYNC16(dst + SB_HALF + n * SB_ROW + seg * 16, lo + (size_t)n * ldk + kbase + seg * 8);
    }
}

__device__ __forceinline__ void hmma_gemm_k256(const float* __restrict__ sA, uint32_t sB,
                                               const __nv_bfloat16* __restrict__ Whi,
                                               const __nv_bfloat16* __restrict__ Wlo,
                                               int ldk, float acc[2][16][4],
                                               int tid, bool zero_acc) {
    if (zero_acc) {
#pragma unroll
        for (int mt = 0; mt < 2; mt++)
#pragma unroll
            for (int nt = 0; nt < 16; nt++)
#pragma unroll
                for (int i = 0; i < 4; i++) acc[mt][nt][i] = 0.f;
    }
    const int lane = tid & 31;
    const int wm = (tid >> 5) & 3, wn = tid >> 7;
    const int gid = lane >> 2, qid = lane & 3;

    issue_chunk(sB, 0, Whi, Wlo, ldk, 0, tid);
    CP_COMMIT();

    for (int kc = 0; kc < 8; kc++) {
        if (kc < 7) {
            issue_chunk(sB, (kc + 1) & 1, Whi, Wlo, ldk, (kc + 1) * 32, tid);
            CP_COMMIT();
            CP_WAIT1();
        } else {
            CP_WAIT0();
        }
        __syncthreads();
        uint32_t sbuf = sB + (uint32_t)(kc & 1) * SB_BUF;
#pragma unroll
        for (int kt = 0; kt < 2; kt++) {
            uint32_t ah[2][4], al[2][4];
#pragma unroll
            for (int mt = 0; mt < 2; mt++) {
                int r0 = wm * 32 + mt * 16 + gid;
                int c0 = kc * 32 + kt * 16 + qid * 2;
                float2 x0 = *(const float2*)(sA + r0 * SA_STRIDE + c0);
                float2 x1 = *(const float2*)(sA + (r0 + 8) * SA_STRIDE + c0);
                float2 x2 = *(const float2*)(sA + r0 * SA_STRIDE + c0 + 8);
                float2 x3 = *(const float2*)(sA + (r0 + 8) * SA_STRIDE + c0 + 8);
                split2(x0, ah[mt][0], al[mt][0]);
                split2(x1, ah[mt][1], al[mt][1]);
                split2(x2, ah[mt][2], al[mt][2]);
                split2(x3, ah[mt][3], al[mt][3]);
            }
#pragma unroll
            for (int nt = 0; nt < 16; nt++) {
                uint32_t ba = sbuf + (uint32_t)((wn * 128 + nt * 8 + gid) * SB_ROW
                                                + kt * 32 + qid * 4);
                uint32_t bh[2], bl[2];
                LDS32(bh[0], ba);
                LDS32(bh[1], ba + 16);
                LDS32(bl[0], ba + SB_HALF);
                LDS32(bl[1], ba + SB_HALF + 16);
#pragma unroll
                for (int mt = 0; mt < 2; mt++) {
                    MMA16816(acc[mt][nt], ah[mt], bh);
                    MMA16816(acc[mt][nt], ah[mt], bl);
                    MMA16816(acc[mt][nt], al[mt], bh);
                }
            }
        }
        __syncthreads();
    }
}

// Fill sA (128 x 256, stride SA_STRIDE) from gmem rows [src + row*ld, 256 cols)
__device__ __forceinline__ void fill_sA(float* sA, const float* __restrict__ src,
                                        int ld, int tid) {
#pragma unroll
    for (int i = 0; i < 32; i++) {
        int e = i * 256 + tid;
        int row = e >> 6;
        int c4 = (e & 63) * 4;
        float4 v = *(const float4*)(src + (size_t)row * ld + c4);
        *(float4*)(sA + row * SA_STRIDE + c4) = v;
    }
}

// Per-fragment index helper
#define FRAG_SETUP() \
    const int lane = tid & 31; \
    const int wm = (tid >> 5) & 3, wn = tid >> 7; \
    const int gid = lane >> 2, qid = lane & 3;

// ===========================================================================
// Fused plate kernel (HMMA): 128 rows per CTA.
//   df    = g - sigmoid(l @ W_eq + b_eq)
//   delta = alpha*(df @ W_tr + b_tr)
//   ASC: out = g - delta       DESC: out = l + delta @ W_ab + b_ab
// ===========================================================================
template <bool DESC>
__global__ __launch_bounds__(256, 1) void plate_hmma(
    const float* __restrict__ g_in, const float* __restrict__ l_in,
    float* __restrict__ out,
    const float* __restrict__ b_eq, const float* __restrict__ b_tr,
    const float* __restrict__ b_ab, const float* __restrict__ alpha_p) {
    extern __shared__ char sm[];
    float* sA = (float*)sm;
    uint32_t sB = smem_to_u32(sm + SA_BYTES);
    const int tid = threadIdx.x;
    const size_t rowbase = (size_t)blockIdx.x * 128;
    FRAG_SETUP();

    fill_sA(sA, l_in + rowbase * 256, 256, tid);

    float acc[2][16][4];
    // GEMM 1: l @ W_eq
    hmma_gemm_k256(sA, sB, WT_eq, WT_eq + 256 * 256, 256, acc, tid, true);

    // Epilogue 1: df = g - sigmoid(acc + b_eq) -> sA
#pragma unroll
    for (int mt = 0; mt < 2; mt++) {
#pragma unroll
        for (int nt = 0; nt < 16; nt++) {
            int col = wn * 128 + nt * 8 + qid * 2;
            int r = wm * 32 + mt * 16 + gid;
            size_t ro = (rowbase + r) * 256 + col;
            float2 be = *(const float2*)(b_eq + col);
            float2 g0 = *(const float2*)(g_in + ro);
            float2 g1 = *(const float2*)(g_in + ro + 8 * 256);
            float2 d0, d1;
            d0.x = g0.x - sigm(acc[mt][nt][0] + be.x);
            d0.y = g0.y - sigm(acc[mt][nt][1] + be.y);
            d1.x = g1.x - sigm(acc[mt][nt][2] + be.x);
            d1.y = g1.y - sigm(acc[mt][nt][3] + be.y);
            *(float2*)(sA + r * SA_STRIDE + col) = d0;
            *(float2*)(sA + (r + 8) * SA_STRIDE + col) = d1;
        }
    }

    // GEMM 2: df @ W_tr
    hmma_gemm_k256(sA, sB, WT_tr, WT_tr + 256 * 256, 256, acc, tid, true);

    const float alpha = *alpha_p;

    if (!DESC) {
        // out = g - alpha*(acc + b_tr)
#pragma unroll
        for (int mt = 0; mt < 2; mt++) {
#pragma unroll
            for (int nt = 0; nt < 16; nt++) {
                int col = wn * 128 + nt * 8 + qid * 2;
                int r = wm * 32 + mt * 16 + gid;
                size_t ro = (rowbase + r) * 256 + col;
                float2 bt = *(const float2*)(b_tr + col);
                float2 g0 = *(const float2*)(g_in + ro);
                float2 g1 = *(const float2*)(g_in + ro + 8 * 256);
                float2 o0, o1;
                o0.x = g0.x - alpha * (acc[mt][nt][0] + bt.x);
                o0.y = g0.y - alpha * (acc[mt][nt][1] + bt.y);
                o1.x = g1.x - alpha * (acc[mt][nt][2] + bt.x);
                o1.y = g1.y - alpha * (acc[mt][nt][3] + bt.y);
                *(float2*)(out + ro) = o0;
                *(float2*)(out + ro + 8 * 256) = o1;
            }
        }
    } else {
        // delta = alpha*(acc + b_tr) -> sA
#pragma unroll
        for (int mt = 0; mt < 2; mt++) {
#pragma unroll
            for (int nt = 0; nt < 16; nt++) {
                int col = wn * 128 + nt * 8 + qid * 2;
                int r = wm * 32 + mt * 16 + gid;
                float2 bt = *(const float2*)(b_tr + col);
                float2 d0, d1;
                d0.x = alpha * (acc[mt][nt][0] + bt.x);
                d0.y = alpha * (acc[mt][nt][1] + bt.y);
                d1.x = alpha * (acc[mt][nt][2] + bt.x);
                d1.y = alpha * (acc[mt][nt][3] + bt.y);
                *(float2*)(sA + r * SA_STRIDE + col) = d0;
                *(float2*)(sA + (r + 8) * SA_STRIDE + col) = d1;
            }
        }

        // GEMM 3: delta @ W_ab
        hmma_gemm_k256(sA, sB, WT_ab, WT_ab + 256 * 256, 256, acc, tid, true);

        // out = l + acc + b_ab
#pragma unroll
        for (int mt = 0; mt < 2; mt++) {
#pragma unroll
            for (int nt = 0; nt < 16; nt++) {
                int col = wn * 128 + nt * 8 + qid * 2;
                int r = wm * 32 + mt * 16 + gid;
                size_t ro = (rowbase + r) * 256 + col;
                float2 ba = *(const float2*)(b_ab + col);
                float2 l0 = *(const float2*)(l_in + ro);
                float2 l1 = *(const float2*)(l_in + ro + 8 * 256);
                float2 o0, o1;
                o0.x = l0.x + acc[mt][nt][0] + ba.x;
                o0.y = l0.y + acc[mt][nt][1] + ba.y;
                o1.x = l1.x + acc[mt][nt][2] + ba.x;
                o1.y = l1.y + acc[mt][nt][3] + ba.y;
                *(float2*)(out + ro) = o0;
                *(float2*)(out + ro + 8 * 256) = o1;
            }
        }
    }
}

// ===========================================================================
// Encoder: g0 = relu(x @ W_ge + b_ge), K = 512 as two accumulated K=256 passes
// ===========================================================================
__global__ __launch_bounds__(256, 1) void encoder_hmma(
    const float* __restrict__ x, const float* __restrict__ b_ge,
    float* __restrict__ g0) {
    extern __shared__ char sm[];
    float* sA = (float*)sm;
    uint32_t sB = smem_to_u32(sm + SA_BYTES);
    const int tid = threadIdx.x;
    const size_t rowbase = (size_t)blockIdx.x * 128;
    FRAG_SETUP();

    float acc[2][16][4];
    fill_sA(sA, x + rowbase * 512, 512, tid);
    hmma_gemm_k256(sA, sB, WT_ge, WT_ge + 256 * 512, 512, acc, tid, true);
    fill_sA(sA, x + rowbase * 512 + 256, 512, tid);
    hmma_gemm_k256(sA, sB, WT_ge + 256, WT_ge + 256 * 512 + 256, 512, acc, tid, false);

#pragma unroll
    for (int mt = 0; mt < 2; mt++) {
#pragma unroll
        for (int nt = 0; nt < 16; nt++) {
            int col = wn * 128 + nt * 8 + qid * 2;
            int r = wm * 32 + mt * 16 + gid;
            size_t ro = (rowbase + r) * 256 + col;
            float2 b = *(const float2*)(b_ge + col);
            float2 o0, o1;
            o0.x = fmaxf(acc[mt][nt][0] + b.x, 0.f);
            o0.y = fmaxf(acc[mt][nt][1] + b.y, 0.f);
            o1.x = fmaxf(acc[mt][nt][2] + b.x, 0.f);
            o1.y = fmaxf(acc[mt][nt][3] + b.y, 0.f);
            *(float2*)(g0 + ro) = o0;
            *(float2*)(g0 + ro + 8 * 256) = o1;
        }
    }
}

// ===========================================================================
// Head: h = relu([g8||l1] @ W1 + b1); out = h @ W2 + b2  (N=1000, 4 tiles)
// ===========================================================================
__global__ __launch_bounds__(256, 1) void head_hmma(
    const float* __restrict__ g8, const float* __restrict__ l1,
    const float* __restrict__ b1, const float* __restrict__ b2,
    float* __restrict__ out) {
    extern __shared__ char sm[];
    float* sA = (float*)sm;
    uint32_t sB = smem_to_u32(sm + SA_BYTES);
    const int tid = threadIdx.x;
    const size_t rowbase = (size_t)blockIdx.x * 128;
    FRAG_SETUP();

    float acc[2][16][4];
    fill_sA(sA, g8 + rowbase * 256, 256, tid);
    hmma_gemm_k256(sA, sB, WT_1, WT_1 + 256 * 512, 512, acc, tid, true);
    fill_sA(sA, l1 + rowbase * 256, 256, tid);
    hmma_gemm_k256(sA, sB, WT_1 + 256, WT_1 + 256 * 512 + 256, 512, acc, tid, false);

    // h = relu(acc + b1) -> sA
#pragma unroll
    for (int mt = 0; mt < 2; mt++) {
#pragma unroll
        for (int nt = 0; nt < 16; nt++) {
            int col = wn * 128 + nt * 8 + qid * 2;
            int r = wm * 32 + mt * 16 + gid;
            float2 b = *(const float2*)(b1 + col);
            float2 h0, h1;
            h0.x = fmaxf(acc[mt][nt][0] + b.x, 0.f);
            h0.y = fmaxf(acc[mt][nt][1] + b.y, 0.f);
            h1.x = fmaxf(acc[mt][nt][2] + b.x, 0.f);
            h1.y = fmaxf(acc[mt][nt][3] + b.y, 0.f);
            *(float2*)(sA + r * SA_STRIDE + col) = h0;
            *(float2*)(sA + (r + 8) * SA_STRIDE + col) = h1;
        }
    }

    for (int t = 0; t < 4; t++) {
        hmma_gemm_k256(sA, sB, WT_2 + (size_t)t * 256 * 256,
                       WT_2 + 1024 * 256 + (size_t)t * 256 * 256, 256, acc, tid, true);
#pragma unroll
        for (int mt = 0; mt < 2; mt++) {
#pragma unroll
            for (int nt = 0; nt < 16; nt++) {
                int col = t * 256 + wn * 128 + nt * 8 + qid * 2;
                if (col < 1000) {
                    int r = wm * 32 + mt * 16 + gid;
                    size_t ro = (rowbase + r) * 1000 + col;
                    float2 b = *(const float2*)(b2 + col);
                    float2 o0, o1;
                    o0.x = acc[mt][nt][0] + b.x;
                    o0.y = acc[mt][nt][1] + b.y;
                    o1.x = acc[mt][nt][2] + b.x;
                    o1.y = acc[mt][nt][3] + b.y;
                    *(float2*)(out + ro) = o0;
                    *(float2*)(out + ro + 8 * 1000) = o1;
                }
            }
        }
    }
}

// ===========================================================================
extern "C" void kernel_launch(void* const* d_in, const int* in_sizes, int n_in,
                              void* d_out, int out_size) {
    (void)in_sizes; (void)n_in; (void)out_size;
    const float* x     = (const float*)d_in[0];
    const float* W_ge  = (const float*)d_in[1];
    const float* b_ge  = (const float*)d_in[2];
    const float* W_eq  = (const float*)d_in[3];
    const float* b_eq  = (const float*)d_in[4];
    const float* W_tr  = (const float*)d_in[5];
    const float* b_tr  = (const float*)d_in[6];
    const float* W_ab  = (const float*)d_in[7];
    const float* b_ab  = (const float*)d_in[8];
    const float* alpha = (const float*)d_in[9];
    const float* W1    = (const float*)d_in[10];
    const float* b1    = (const float*)d_in[11];
    const float* W2    = (const float*)d_in[12];
    const float* b2    = (const float*)d_in[13];
    float* out = (float*)d_out;

    float *gb = nullptr, *lb = nullptr;
    cudaGetSymbolAddress((void**)&gb, g_bufs);
    cudaGetSymbolAddress((void**)&lb, l_bufs);
    auto G = [&](int i) { return gb + (size_t)i * BATCH * DG; };
    auto L = [&](int i) { return lb + (size_t)i * BATCH * DG; };

    cudaFuncSetAttribute(plate_hmma<true>,  cudaFuncAttributeMaxDynamicSharedMemorySize, SMEM_TOTAL);
    cudaFuncSetAttribute(plate_hmma<false>, cudaFuncAttributeMaxDynamicSharedMemorySize, SMEM_TOTAL);
    cudaFuncSetAttribute(encoder_hmma,      cudaFuncAttributeMaxDynamicSharedMemorySize, SMEM_TOTAL);
    cudaFuncSetAttribute(head_hmma,         cudaFuncAttributeMaxDynamicSharedMemorySize, SMEM_TOTAL);

    cudaMemsetAsync(L(9), 0, (size_t)BATCH * DG * sizeof(float));
    prep_kernel<<<256, 256>>>(W_ge, W_eq, W_tr, W_ab, W1, W2);

    dim3 grid(BATCH / 128);

    encoder_hmma<<<grid, 256, SMEM_TOTAL>>>(x, b_ge, G(0));

    // Sweep 1: descending (g[1..8] None -> g_in = g0)
    for (int n = 8; n >= 1; --n)
        plate_hmma<true><<<grid, 256, SMEM_TOTAL>>>(G(0), L(n + 1), L(n),
                                                    b_eq, b_tr, b_ab, alpha);
    // Sweep 1: ascending
    for (int n = 1; n <= 8; ++n)
        plate_hmma<false><<<grid, 256, SMEM_TOTAL>>>(G(n - 1), L(n), G(n),
                                                     b_eq, b_tr, b_ab, alpha);
    // Sweep 2: descending
    for (int n = 8; n >= 1; --n)
        plate_hmma<true><<<grid, 256, SMEM_TOTAL>>>(G(n - 1), L(n + 1), L(n),
                                                    b_eq, b_tr, b_ab, alpha);
    // Sweep 2: ascending
    for (int n = 1; n <= 8; ++n)
        plate_hmma<false><<<grid, 256, SMEM_TOTAL>>>(G(n - 1), L(n), G(n),
                                                     b_eq, b_tr, b_ab, alpha);

    head_hmma<<<grid, 256, SMEM_TOTAL>>>(G(8), L(1), b1, b2, out);
}